// round 15
// baseline (speedup 1.0000x reference)
#include <cuda_runtime.h>
#include <cuda_bf16.h>
#include <math.h>
#include <stdint.h>

#define B_ 1024
#define T_ 128
#define MX_ (B_ * T_)

__device__ float g_buf1[MX_ * 128];
__device__ float g_buf2[MX_ * 64];
__device__ float g_buf3[B_ * 32];
__device__ float g_xzf[MX_ * 256];
__device__ float g_xzb[MX_ * 256];
// Pre-packed split-bf16 weights, layout [dir][pp * NGL + n] (pp = k-pair).
__device__ uint32_t g_w1h[2 * 40 * 256], g_w1l[2 * 40 * 256];
__device__ uint32_t g_w2h[2 * 64 * 128], g_w2l[2 * 64 * 128];
__device__ uint32_t g_w3h[2 * 32 * 64],  g_w3l[2 * 32 * 64];

__device__ __forceinline__ float sigf(float x) {
    return __fdividef(1.0f, 1.0f + __expf(-x));
}
__device__ __forceinline__ float tanhf_fast(float x) {
    return __fdividef(2.0f, 1.0f + __expf(-2.0f * x)) - 1.0f;
}

// ---- packed f32x2 helpers ----
typedef unsigned long long u64t;
__device__ __forceinline__ u64t packf2(float lo, float hi) {
    u64t r; asm("mov.b64 %0, {%1, %2};" : "=l"(r) : "f"(lo), "f"(hi)); return r;
}
__device__ __forceinline__ void fma2(u64t& d, u64t a, u64t b) {
    asm("fma.rn.f32x2 %0, %1, %2, %0;" : "+l"(d) : "l"(a), "l"(b));
}
__device__ __forceinline__ void add2(u64t& d, u64t a) {
    asm("add.rn.f32x2 %0, %0, %1;" : "+l"(d) : "l"(a));
}
__device__ __forceinline__ void unpack2(float& lo, float& hi, u64t v) {
    asm("mov.b64 {%0, %1}, %2;" : "=f"(lo), "=f"(hi) : "l"(v));
}

__device__ __forceinline__ uint32_t pack_split(float v0, float v1, uint32_t& lo) {
    __nv_bfloat16 h0 = __float2bfloat16(v0);
    __nv_bfloat16 h1 = __float2bfloat16(v1);
    float r0 = v0 - __bfloat162float(h0);
    float r1 = v1 - __bfloat162float(h1);
    __nv_bfloat16 l0 = __float2bfloat16(r0);
    __nv_bfloat16 l1 = __float2bfloat16(r1);
    lo = ((uint32_t)__bfloat16_as_ushort(l1) << 16) | (uint32_t)__bfloat16_as_ushort(l0);
    return ((uint32_t)__bfloat16_as_ushort(h1) << 16) | (uint32_t)__bfloat16_as_ushort(h0);
}

__device__ __forceinline__ void mma_bf16(float* c, const uint32_t* a, uint32_t b0, uint32_t b1) {
    asm volatile(
        "mma.sync.aligned.m16n8k16.row.col.f32.bf16.bf16.f32 "
        "{%0,%1,%2,%3}, {%4,%5,%6,%7}, {%8,%9}, {%0,%1,%2,%3};\n"
        : "+f"(c[0]), "+f"(c[1]), "+f"(c[2]), "+f"(c[3])
        : "r"(a[0]), "r"(a[1]), "r"(a[2]), "r"(a[3]), "r"(b0), "r"(b1));
}

// ---------------------------------------------------------------------------
// Weight pack: W [K, NGL] fp32 -> [dir][pp*NGL + n] split-bf16 u32 pairs.
// ---------------------------------------------------------------------------
template <int K, int KPH, int NGL>
__global__ void pack_w(const float* __restrict__ Wf, const float* __restrict__ Wb,
                       uint32_t* __restrict__ outH, uint32_t* __restrict__ outL)
{
    const int dir = blockIdx.y;
    const float* W = dir ? Wb : Wf;
    uint32_t* oh = outH + (size_t)dir * KPH * NGL;
    uint32_t* ol = outL + (size_t)dir * KPH * NGL;
    int idx = blockIdx.x * 256 + threadIdx.x;
    if (idx >= KPH * NGL) return;
    int pp = idx / NGL, n = idx % NGL;
    int k0 = 2 * pp;
    float w0 = (k0 < K)     ? W[(size_t)k0 * NGL + n]       : 0.0f;
    float w1 = (k0 + 1 < K) ? W[(size_t)(k0 + 1) * NGL + n] : 0.0f;
    uint32_t lo;
    uint32_t hi = pack_split(w0, w1, lo);
    oh[idx] = hi;
    ol[idx] = lo;
}

// ---------------------------------------------------------------------------
// Split-bf16 GEMM v6 (R14-validated, unchanged).
// ---------------------------------------------------------------------------
template <int K, int KP, int NGL, int NW>
__global__ void __launch_bounds__(NW * 32) inproj_gemm(
    const float* __restrict__ X,
    const uint32_t* __restrict__ WhiG, const uint32_t* __restrict__ WloG,
    const float* __restrict__ bfv, const float* __restrict__ bbv,
    float* __restrict__ outf, float* __restrict__ outb)
{
    constexpr int NT  = NW * 32;
    constexpr int KPH = KP / 2;
    constexpr int KC  = KP / 16;
    constexpr int NTW = NGL / (8 * NW);
    constexpr int FRAG = 8 * KC * 128;

    extern __shared__ uint32_t smu[];
    uint32_t* AhiF = smu;
    uint32_t* AloF = AhiF + FRAG;

    const int dir = blockIdx.y;
    const uint32_t* Whi = WhiG + (size_t)dir * KPH * NGL;
    const uint32_t* Wlo = WloG + (size_t)dir * KPH * NGL;
    const float* bias = dir ? bbv : bfv;
    float* out = dir ? outb : outf;
    const int m0 = blockIdx.x * 128;
    const int tid = threadIdx.x;

    for (int i = tid; i < 128 * KPH; i += NT) {
        int row = i / KPH, pp = i % KPH;
        int k0 = 2 * pp;
        float v0 = 0.0f, v1 = 0.0f;
        if (k0 + 1 < K) {
            float2 xv = *(const float2*)&X[(size_t)(m0 + row) * K + k0];
            v0 = xv.x; v1 = xv.y;
        } else if (k0 < K) {
            v0 = X[(size_t)(m0 + row) * K + k0];
        }
        uint32_t lo;
        uint32_t hi = pack_split(v0, v1, lo);
        int mt = row >> 4, rr = row & 15;
        int b1 = rr >> 3, g = rr & 7;
        int kc = pp >> 3, q = pp & 7;
        int b2 = q >> 2, i4 = q & 3;
        int lane = g * 4 + i4;
        int fi = b1 + 2 * b2;
        int idx = ((mt * KC + kc) * 32 + lane) * 4 + fi;
        AhiF[idx] = hi;
        AloF[idx] = lo;
    }
    __syncthreads();

    const int wid = tid >> 5, lane = tid & 31;
    const int g = lane >> 2, i4 = lane & 3;
    const int n0 = wid * (NGL / NW);

    uint32_t bh0c[KC][NTW], bh1c[KC][NTW], bl0c[KC][NTW], bl1c[KC][NTW];
#pragma unroll
    for (int kc = 0; kc < KC; ++kc)
#pragma unroll
        for (int nt = 0; nt < NTW; ++nt) {
            int nn = n0 + nt * 8 + g;
            int p0 = kc * 8 + i4;
            int p1 = kc * 8 + 4 + i4;
            bh0c[kc][nt] = (p0 < KPH) ? Whi[p0 * NGL + nn] : 0u;
            bh1c[kc][nt] = (p1 < KPH) ? Whi[p1 * NGL + nn] : 0u;
            bl0c[kc][nt] = (p0 < KPH) ? Wlo[p0 * NGL + nn] : 0u;
            bl1c[kc][nt] = (p1 < KPH) ? Wlo[p1 * NGL + nn] : 0u;
        }

#pragma unroll
    for (int mt = 0; mt < 8; ++mt) {
        const int mrow = mt * 16;
        float acc[NTW][4];
#pragma unroll
        for (int nt = 0; nt < NTW; ++nt)
#pragma unroll
            for (int q = 0; q < 4; ++q) acc[nt][q] = 0.0f;

#pragma unroll
        for (int kc = 0; kc < KC; ++kc) {
            const uint4 ah4 = *(const uint4*)&AhiF[((mt * KC + kc) * 32 + lane) * 4];
            const uint4 al4 = *(const uint4*)&AloF[((mt * KC + kc) * 32 + lane) * 4];
            uint32_t ahi[4] = {ah4.x, ah4.y, ah4.z, ah4.w};
            uint32_t alo[4] = {al4.x, al4.y, al4.z, al4.w};
#pragma unroll
            for (int nt = 0; nt < NTW; ++nt) {
                mma_bf16(acc[nt], ahi, bh0c[kc][nt], bh1c[kc][nt]);
                mma_bf16(acc[nt], ahi, bl0c[kc][nt], bl1c[kc][nt]);
                mma_bf16(acc[nt], alo, bh0c[kc][nt], bh1c[kc][nt]);
            }
        }

#pragma unroll
        for (int nt = 0; nt < NTW; ++nt) {
            int n = n0 + nt * 8 + 2 * i4;
            float bx = bias[n], by = bias[n + 1];
            size_t r = (size_t)(m0 + mrow + g);
            *(float2*)&out[r * NGL + n]       = make_float2(acc[nt][0] + bx, acc[nt][1] + by);
            *(float2*)&out[(r + 8) * NGL + n] = make_float2(acc[nt][2] + bx, acc[nt][3] + by);
        }
    }
}

// ---------------------------------------------------------------------------
// L1 recurrence v6: v4 topology + FFMA2 with zero critical-path packing.
// Block 256 thr = (kh:2) x (rg:2) x (unit:64), 8 rows/block, grid (B/8, 2).
// Weights SMEM gate-interleaved [u2][u][4] read as ulonglong2 -> (wi,wf),(wg,wo).
// h stored DUPLICATED: hd[row][u2][2]; one ulonglong2 read = (h,h),(h',h').
// Per thread per step: 256 FFMA2 (was 512 FFMA). kh=1 passes packed partials.
// ---------------------------------------------------------------------------
__global__ void __launch_bounds__(256) lstm_rec_l1(
    const float* __restrict__ xzf, const float* __restrict__ xzb,  // [MX,256]
    const float* __restrict__ Wrf, const float* __restrict__ Wrb,  // [64,256]
    float* __restrict__ out)                                        // [B,T,128]
{
    extern __shared__ float sm[];
    float* Wr_s = sm;                        // 64*256 floats (64 KB)
    float* hd0  = Wr_s + 64 * 256;           // 8*64*2 = 1024 floats (4 KB)
    float* hd1  = hd0 + 1024;                // 1024 floats (4 KB)
    ulonglong2* ps = (ulonglong2*)(hd1 + 1024);  // [8][64] (8 KB)

    const int dir = blockIdx.y;
    const float* Wr = dir ? Wrb : Wrf;
    const float* xz = dir ? xzb : xzf;

    const int tid = threadIdx.x;
    const int u   = tid & 63;
    const int r0  = ((tid >> 6) & 1) * 4;
    const int kh  = tid >> 7;
    const int b0  = blockIdx.x * 8;

    for (int i = tid; i < 64 * 256; i += 256) {
        int u2 = i >> 8, c = i & 255, uu = c >> 2, gg = c & 3;
        Wr_s[i] = Wr[u2 * 256 + gg * 64 + uu];
    }
    for (int i = tid; i < 2048; i += 256) { hd0[i] = 0.0f; hd1[i] = 0.0f; }

    float cst[4];
    u64t cxif[4], cxgo[4];
#pragma unroll
    for (int j = 0; j < 4; ++j) cst[j] = 0.0f;
    if (kh == 0) {
        const int t0 = dir ? (T_ - 1) : 0;
#pragma unroll
        for (int j = 0; j < 4; ++j) {
            const float* p = xz + ((size_t)(b0 + r0 + j) * T_ + t0) * 256;
            cxif[j] = packf2(p[u], p[64 + u]);
            cxgo[j] = packf2(p[128 + u], p[192 + u]);
        }
    }
    __syncthreads();

    const ulonglong2* __restrict__ wrp = (const ulonglong2*)Wr_s;   // [u2*64 + u]
    float* hc = hd0; float* hn_ = hd1;

    for (int s = 0; s < T_; ++s) {
        const int t  = dir ? (T_ - 1 - s) : s;
        const int sn = (s + 1 < T_) ? (s + 1) : s;
        const int tn = dir ? (T_ - 1 - sn) : sn;

        u64t pif[4], pgo[4];
        if (kh == 0) {
#pragma unroll
            for (int j = 0; j < 4; ++j) {
                const float* p = xz + ((size_t)(b0 + r0 + j) * T_ + tn) * 256;
                pif[j] = packf2(p[u], p[64 + u]);
                pgo[j] = packf2(p[128 + u], p[192 + u]);
            }
        }

        u64t aif[4], ago[4];
        if (kh == 0) {
#pragma unroll
            for (int j = 0; j < 4; ++j) { aif[j] = cxif[j]; ago[j] = cxgo[j]; }
        } else {
#pragma unroll
            for (int j = 0; j < 4; ++j) { aif[j] = 0; ago[j] = 0; }
        }

        // Recurrent half-sum: 32 u2 (this kh), paired gates via FFMA2.
#pragma unroll
        for (int j2 = 0; j2 < 16; ++j2) {
            const int u2b = kh * 32 + j2 * 2;
            ulonglong2 hp[4];
#pragma unroll
            for (int j = 0; j < 4; ++j)
                hp[j] = *(const ulonglong2*)&hc[((r0 + j) * 64 + u2b) * 2];
            ulonglong2 w0 = wrp[u2b * 64 + u];
            ulonglong2 w1 = wrp[(u2b + 1) * 64 + u];
#pragma unroll
            for (int j = 0; j < 4; ++j) {
                fma2(aif[j], hp[j].x, w0.x); fma2(ago[j], hp[j].x, w0.y);
                fma2(aif[j], hp[j].y, w1.x); fma2(ago[j], hp[j].y, w1.y);
            }
        }

        if (kh == 1) {
#pragma unroll
            for (int j = 0; j < 4; ++j)
                ps[(r0 + j) * 64 + u] = make_ulonglong2(aif[j], ago[j]);
        }
        __syncthreads();

        if (kh == 0) {
#pragma unroll
            for (int j = 0; j < 4; ++j) {
                ulonglong2 q2 = ps[(r0 + j) * 64 + u];
                add2(aif[j], q2.x); add2(ago[j], q2.y);
                float ai, af, ag, ao;
                unpack2(ai, af, aif[j]);
                unpack2(ag, ao, ago[j]);
                float ig = sigf(ai);
                float fg = sigf(af);
                float gg = tanhf_fast(ag);
                float og = sigf(ao);
                cst[j] = fg * cst[j] + ig * gg;
                float hn = og * tanhf_fast(cst[j]);
                *(float2*)&hn_[((r0 + j) * 64 + u) * 2] = make_float2(hn, hn);
                out[((size_t)(b0 + r0 + j) * T_ + t) * 128 + dir * 64 + u] = hn;
                cxif[j] = pif[j]; cxgo[j] = pgo[j];
            }
        }
        __syncthreads();
        float* tmp = hc; hc = hn_; hn_ = tmp;
    }
}

// ---------------------------------------------------------------------------
// L2 recurrence (U=32): R6-exact sync-free 2-rows/warp (96.6us, measured).
// ---------------------------------------------------------------------------
__global__ void __launch_bounds__(128) lstm_rec_l2(
    const float* __restrict__ xzf, const float* __restrict__ xzb,
    const float* __restrict__ Wrf, const float* __restrict__ Wrb,
    float* __restrict__ out)
{
    __shared__ float hsm[4][2][2][32];

    const int dir = blockIdx.y;
    const float* Wr = dir ? Wrb : Wrf;
    const float* xz = dir ? xzb : xzf;

    const int tid = threadIdx.x, wid = tid >> 5, lane = tid & 31;
    const size_t rb0 = (size_t)(blockIdx.x * 8 + wid * 2) * T_;
    const size_t rb1 = rb0 + T_;

    float4 wq[32];
#pragma unroll
    for (int u2 = 0; u2 < 32; ++u2) {
        const float* wrow = Wr + u2 * 128;
        wq[u2] = make_float4(wrow[lane], wrow[32 + lane], wrow[64 + lane], wrow[96 + lane]);
    }

    float c0 = 0.0f, c1 = 0.0f;
    float4 cx0, cx1;
    {
        const int t0 = dir ? (T_ - 1) : 0;
        const float* p0 = xz + (rb0 + t0) * 128;
        const float* p1 = xz + (rb1 + t0) * 128;
        cx0 = make_float4(p0[lane], p0[32 + lane], p0[64 + lane], p0[96 + lane]);
        cx1 = make_float4(p1[lane], p1[32 + lane], p1[64 + lane], p1[96 + lane]);
    }
    hsm[wid][0][0][lane] = 0.0f;
    hsm[wid][0][1][lane] = 0.0f;
    __syncwarp();

    int p = 0;
    for (int s = 0; s < T_; ++s) {
        const int t  = dir ? (T_ - 1 - s) : s;
        const int sn = (s + 1 < T_) ? (s + 1) : s;
        const int tn = dir ? (T_ - 1 - sn) : sn;

        const float* q0 = xz + (rb0 + tn) * 128;
        const float* q1 = xz + (rb1 + tn) * 128;
        float4 pre0 = make_float4(q0[lane], q0[32 + lane], q0[64 + lane], q0[96 + lane]);
        float4 pre1 = make_float4(q1[lane], q1[32 + lane], q1[64 + lane], q1[96 + lane]);

        float4 a0 = cx0, a1 = cx1;
#pragma unroll
        for (int jj = 0; jj < 8; ++jj) {
            float4 h40 = *(const float4*)&hsm[wid][p][0][jj * 4];
            float4 h41 = *(const float4*)&hsm[wid][p][1][jj * 4];
#pragma unroll
            for (int q = 0; q < 4; ++q) {
                float hv0 = (&h40.x)[q], hv1 = (&h41.x)[q];
                float4 w = wq[jj * 4 + q];
                a0.x += hv0 * w.x; a0.y += hv0 * w.y; a0.z += hv0 * w.z; a0.w += hv0 * w.w;
                a1.x += hv1 * w.x; a1.y += hv1 * w.y; a1.z += hv1 * w.z; a1.w += hv1 * w.w;
            }
        }

        float i0 = sigf(a0.x), f0 = sigf(a0.y), g0 = tanhf_fast(a0.z), o0 = sigf(a0.w);
        c0 = f0 * c0 + i0 * g0;
        float h0 = o0 * tanhf_fast(c0);
        float i1 = sigf(a1.x), f1 = sigf(a1.y), g1 = tanhf_fast(a1.z), o1 = sigf(a1.w);
        c1 = f1 * c1 + i1 * g1;
        float h1 = o1 * tanhf_fast(c1);

        hsm[wid][p ^ 1][0][lane] = h0;
        hsm[wid][p ^ 1][1][lane] = h1;
        out[(rb0 + t) * 64 + dir * 32 + lane] = h0;
        out[(rb1 + t) * 64 + dir * 32 + lane] = h1;
        cx0 = pre0; cx1 = pre1;
        __syncwarp();
        p ^= 1;
    }
}

__global__ void __launch_bounds__(128) lstm_rec_l3(
    const float* __restrict__ xzf, const float* __restrict__ xzb,
    const float* __restrict__ Wrf, const float* __restrict__ Wrb,
    float* __restrict__ out)
{
    __shared__ float hsm[4][2][2][16];

    const int dir = blockIdx.y;
    const float* Wr = dir ? Wrb : Wrf;
    const float* xz = dir ? xzb : xzf;

    const int tid = threadIdx.x, wid = tid >> 5, lane = tid & 31;
    const int r2 = lane >> 4, u = lane & 15;
    const int row = blockIdx.x * 8 + wid * 2 + r2;
    const size_t rb = (size_t)row * T_;

    float4 wq[16];
#pragma unroll
    for (int u2 = 0; u2 < 16; ++u2) {
        const float* wrow = Wr + u2 * 64;
        wq[u2] = make_float4(wrow[u], wrow[16 + u], wrow[32 + u], wrow[48 + u]);
    }

    float cst = 0.0f, h = 0.0f;
    float4 cx;
    {
        const int t0 = dir ? (T_ - 1) : 0;
        const float* p = xz + (rb + t0) * 64;
        cx = make_float4(p[u], p[16 + u], p[32 + u], p[48 + u]);
    }
    hsm[wid][0][r2][u] = 0.0f;
    __syncwarp();

    int p = 0;
    for (int s = 0; s < T_; ++s) {
        const int sn = (s + 1 < T_) ? (s + 1) : s;
        const int tn = dir ? (T_ - 1 - sn) : sn;

        const float* q = xz + (rb + tn) * 64;
        float4 pre = make_float4(q[u], q[16 + u], q[32 + u], q[48 + u]);

        float4 a = cx;
#pragma unroll
        for (int jj = 0; jj < 4; ++jj) {
            float4 h4 = *(const float4*)&hsm[wid][p][r2][jj * 4];
#pragma unroll
            for (int qq = 0; qq < 4; ++qq) {
                float hv = (&h4.x)[qq];
                float4 wv = wq[jj * 4 + qq];
                a.x += hv * wv.x; a.y += hv * wv.y; a.z += hv * wv.z; a.w += hv * wv.w;
            }
        }

        float ig = sigf(a.x), fg = sigf(a.y), gg = tanhf_fast(a.z), og = sigf(a.w);
        cst = fg * cst + ig * gg;
        h = og * tanhf_fast(cst);

        hsm[wid][p ^ 1][r2][u] = h;
        cx = pre;
        __syncwarp();
        p ^= 1;
    }

    out[row * 32 + dir * 16 + u] = h;
}

__global__ void head_kernel(const float* __restrict__ h3,
                            const float* __restrict__ d3w, const float* __restrict__ d3b,
                            const float* __restrict__ cw,  const float* __restrict__ cb,
                            float* __restrict__ out)
{
    int b = blockIdx.x * blockDim.x + threadIdx.x;
    if (b >= B_) return;

    float hv[32];
#pragma unroll
    for (int i = 0; i < 32; ++i) hv[i] = h3[b * 32 + i];

    float d[8];
#pragma unroll
    for (int j = 0; j < 8; ++j) {
        float a = d3b[j];
#pragma unroll
        for (int i = 0; i < 32; ++i) a += hv[i] * d3w[i * 8 + j];
        d[j] = a > 0.0f ? a : 0.0f;
    }
#pragma unroll
    for (int k = 0; k < 3; ++k) {
        float a = cb[k];
#pragma unroll
        for (int j = 0; j < 8; ++j) a += d[j] * cw[j * 3 + k];
        out[b * 3 + k] = 1.0f / (1.0f + expf(-a));
    }
}

extern "C" void kernel_launch(void* const* d_in, const int* in_sizes, int n_in,
                              void* d_out, int out_size)
{
    const float* x     = (const float*)d_in[0];
    const float* w1f_k = (const float*)d_in[1];
    const float* w1f_r = (const float*)d_in[2];
    const float* w1f_b = (const float*)d_in[3];
    const float* w1b_k = (const float*)d_in[4];
    const float* w1b_r = (const float*)d_in[5];
    const float* w1b_b = (const float*)d_in[6];
    const float* w2f_k = (const float*)d_in[7];
    const float* w2f_r = (const float*)d_in[8];
    const float* w2f_b = (const float*)d_in[9];
    const float* w2b_k = (const float*)d_in[10];
    const float* w2b_r = (const float*)d_in[11];
    const float* w2b_b = (const float*)d_in[12];
    const float* w3f_k = (const float*)d_in[13];
    const float* w3f_r = (const float*)d_in[14];
    const float* w3f_b = (const float*)d_in[15];
    const float* w3b_k = (const float*)d_in[16];
    const float* w3b_r = (const float*)d_in[17];
    const float* w3b_b = (const float*)d_in[18];
    const float* d3_w  = (const float*)d_in[19];
    const float* d3_b  = (const float*)d_in[20];
    const float* cls_w = (const float*)d_in[21];
    const float* cls_b = (const float*)d_in[22];

    float *b1, *b2, *b3, *xzf, *xzb;
    uint32_t *p1h, *p1l, *p2h, *p2l, *p3h, *p3l;
    cudaGetSymbolAddress((void**)&b1, g_buf1);
    cudaGetSymbolAddress((void**)&b2, g_buf2);
    cudaGetSymbolAddress((void**)&b3, g_buf3);
    cudaGetSymbolAddress((void**)&xzf, g_xzf);
    cudaGetSymbolAddress((void**)&xzb, g_xzb);
    cudaGetSymbolAddress((void**)&p1h, g_w1h);
    cudaGetSymbolAddress((void**)&p1l, g_w1l);
    cudaGetSymbolAddress((void**)&p2h, g_w2h);
    cudaGetSymbolAddress((void**)&p2l, g_w2l);
    cudaGetSymbolAddress((void**)&p3h, g_w3h);
    cudaGetSymbolAddress((void**)&p3l, g_w3l);

    const size_t gs1 = (size_t)2 * 8 * 5 * 128 * 4;   // 40 KB
    const size_t gs2 = (size_t)2 * 8 * 8 * 128 * 4;   // 64 KB
    const size_t gs3 = (size_t)2 * 8 * 4 * 128 * 4;   // 32 KB
    const size_t rs1 = (size_t)(64 * 256 + 2048) * 4 + 8 * 64 * 16;  // 64+8+8 = 80 KB

    cudaFuncSetAttribute((const void*)inproj_gemm<78, 80, 256, 16>,
                         cudaFuncAttributeMaxDynamicSharedMemorySize, (int)gs1);
    cudaFuncSetAttribute((const void*)inproj_gemm<128, 128, 128, 16>,
                         cudaFuncAttributeMaxDynamicSharedMemorySize, (int)gs2);
    cudaFuncSetAttribute((const void*)inproj_gemm<64, 64, 64, 8>,
                         cudaFuncAttributeMaxDynamicSharedMemorySize, (int)gs3);
    cudaFuncSetAttribute((const void*)lstm_rec_l1,
                         cudaFuncAttributeMaxDynamicSharedMemorySize, (int)rs1);

    // ---- Pre-pack all weights ----
    pack_w<78, 40, 256><<<dim3((40 * 256 + 255) / 256, 2), 256>>>(w1f_k, w1b_k, p1h, p1l);
    pack_w<128, 64, 128><<<dim3((64 * 128 + 255) / 256, 2), 256>>>(w2f_k, w2b_k, p2h, p2l);
    pack_w<64, 32, 64><<<dim3((32 * 64 + 255) / 256, 2), 256>>>(w3f_k, w3b_k, p3h, p3l);

    // ---- Layer 1 ----
    inproj_gemm<78, 80, 256, 16><<<dim3(MX_ / 128, 2), 512, gs1>>>(
        x, p1h, p1l, w1f_b, w1b_b, xzf, xzb);
    lstm_rec_l1<<<dim3(B_ / 8, 2), 256, rs1>>>(xzf, xzb, w1f_r, w1b_r, b1);

    // ---- Layer 2 ----
    inproj_gemm<128, 128, 128, 16><<<dim3(MX_ / 128, 2), 512, gs2>>>(
        b1, p2h, p2l, w2f_b, w2b_b, xzf, xzb);
    lstm_rec_l2<<<dim3(B_ / 8, 2), 128>>>(xzf, xzb, w2f_r, w2b_r, b2);

    // ---- Layer 3 ----
    inproj_gemm<64, 64, 64, 8><<<dim3(MX_ / 128, 2), 256, gs3>>>(
        b2, p3h, p3l, w3f_b, w3b_b, xzf, xzb);
    lstm_rec_l3<<<dim3(B_ / 8, 2), 128>>>(xzf, xzb, w3f_r, w3b_r, b3);

    // ---- Head ----
    head_kernel<<<(B_ + 255) / 256, 256>>>(b3, d3_w, d3_b, cls_w, cls_b, (float*)d_out);
}

// round 16
// speedup vs baseline: 1.1400x; 1.1400x over previous
#include <cuda_runtime.h>
#include <cuda_bf16.h>
#include <math.h>
#include <stdint.h>

#define B_ 1024
#define T_ 128
#define MX_ (B_ * T_)

__device__ float g_buf1[MX_ * 128];
__device__ float g_buf2[MX_ * 64];
__device__ float g_buf3[B_ * 32];
__device__ float g_xzf[MX_ * 256];
__device__ float g_xzb[MX_ * 256];
// Pre-packed split-bf16 weights, layout [dir][pp * NGL + n] (pp = k-pair).
__device__ uint32_t g_w1h[2 * 40 * 256], g_w1l[2 * 40 * 256];
__device__ uint32_t g_w2h[2 * 64 * 128], g_w2l[2 * 64 * 128];
__device__ uint32_t g_w3h[2 * 32 * 64],  g_w3l[2 * 32 * 64];

__device__ __forceinline__ float sigf(float x) {
    return __fdividef(1.0f, 1.0f + __expf(-x));
}
__device__ __forceinline__ float tanhf_fast(float x) {
    return __fdividef(2.0f, 1.0f + __expf(-2.0f * x)) - 1.0f;
}

__device__ __forceinline__ uint32_t pack_split(float v0, float v1, uint32_t& lo) {
    __nv_bfloat16 h0 = __float2bfloat16(v0);
    __nv_bfloat16 h1 = __float2bfloat16(v1);
    float r0 = v0 - __bfloat162float(h0);
    float r1 = v1 - __bfloat162float(h1);
    __nv_bfloat16 l0 = __float2bfloat16(r0);
    __nv_bfloat16 l1 = __float2bfloat16(r1);
    lo = ((uint32_t)__bfloat16_as_ushort(l1) << 16) | (uint32_t)__bfloat16_as_ushort(l0);
    return ((uint32_t)__bfloat16_as_ushort(h1) << 16) | (uint32_t)__bfloat16_as_ushort(h0);
}

__device__ __forceinline__ void mma_bf16(float* c, const uint32_t* a, uint32_t b0, uint32_t b1) {
    asm volatile(
        "mma.sync.aligned.m16n8k16.row.col.f32.bf16.bf16.f32 "
        "{%0,%1,%2,%3}, {%4,%5,%6,%7}, {%8,%9}, {%0,%1,%2,%3};\n"
        : "+f"(c[0]), "+f"(c[1]), "+f"(c[2]), "+f"(c[3])
        : "r"(a[0]), "r"(a[1]), "r"(a[2]), "r"(a[3]), "r"(b0), "r"(b1));
}

// ---------------------------------------------------------------------------
// Weight pack: W [K, NGL] fp32 -> [dir][pp*NGL + n] split-bf16 u32 pairs.
// ---------------------------------------------------------------------------
template <int K, int KPH, int NGL>
__global__ void pack_w(const float* __restrict__ Wf, const float* __restrict__ Wb,
                       uint32_t* __restrict__ outH, uint32_t* __restrict__ outL)
{
    const int dir = blockIdx.y;
    const float* W = dir ? Wb : Wf;
    uint32_t* oh = outH + (size_t)dir * KPH * NGL;
    uint32_t* ol = outL + (size_t)dir * KPH * NGL;
    int idx = blockIdx.x * 256 + threadIdx.x;
    if (idx >= KPH * NGL) return;
    int pp = idx / NGL, n = idx % NGL;
    int k0 = 2 * pp;
    float w0 = (k0 < K)     ? W[(size_t)k0 * NGL + n]       : 0.0f;
    float w1 = (k0 + 1 < K) ? W[(size_t)(k0 + 1) * NGL + n] : 0.0f;
    uint32_t lo;
    uint32_t hi = pack_split(w0, w1, lo);
    oh[idx] = hi;
    ol[idx] = lo;
}

// ---------------------------------------------------------------------------
// Split-bf16 GEMM v7: v6 + minBlocksPerMultiprocessor=2 (forces regs<=64 ->
// 2 blocks/SM, 32 warps, 2x latency hiding). Arithmetic unchanged.
// ---------------------------------------------------------------------------
template <int K, int KP, int NGL, int NW>
__global__ void __launch_bounds__(NW * 32, 2) inproj_gemm(
    const float* __restrict__ X,
    const uint32_t* __restrict__ WhiG, const uint32_t* __restrict__ WloG,
    const float* __restrict__ bfv, const float* __restrict__ bbv,
    float* __restrict__ outf, float* __restrict__ outb)
{
    constexpr int NT  = NW * 32;
    constexpr int KPH = KP / 2;
    constexpr int KC  = KP / 16;
    constexpr int NTW = NGL / (8 * NW);
    constexpr int FRAG = 8 * KC * 128;

    extern __shared__ uint32_t smu[];
    uint32_t* AhiF = smu;
    uint32_t* AloF = AhiF + FRAG;

    const int dir = blockIdx.y;
    const uint32_t* Whi = WhiG + (size_t)dir * KPH * NGL;
    const uint32_t* Wlo = WloG + (size_t)dir * KPH * NGL;
    const float* bias = dir ? bbv : bfv;
    float* out = dir ? outb : outf;
    const int m0 = blockIdx.x * 128;
    const int tid = threadIdx.x;

    for (int i = tid; i < 128 * KPH; i += NT) {
        int row = i / KPH, pp = i % KPH;
        int k0 = 2 * pp;
        float v0 = 0.0f, v1 = 0.0f;
        if (k0 + 1 < K) {
            float2 xv = *(const float2*)&X[(size_t)(m0 + row) * K + k0];
            v0 = xv.x; v1 = xv.y;
        } else if (k0 < K) {
            v0 = X[(size_t)(m0 + row) * K + k0];
        }
        uint32_t lo;
        uint32_t hi = pack_split(v0, v1, lo);
        int mt = row >> 4, rr = row & 15;
        int b1 = rr >> 3, g = rr & 7;
        int kc = pp >> 3, q = pp & 7;
        int b2 = q >> 2, i4 = q & 3;
        int lane = g * 4 + i4;
        int fi = b1 + 2 * b2;
        int idx = ((mt * KC + kc) * 32 + lane) * 4 + fi;
        AhiF[idx] = hi;
        AloF[idx] = lo;
    }
    __syncthreads();

    const int wid = tid >> 5, lane = tid & 31;
    const int g = lane >> 2, i4 = lane & 3;
    const int n0 = wid * (NGL / NW);

    uint32_t bh0c[KC][NTW], bh1c[KC][NTW], bl0c[KC][NTW], bl1c[KC][NTW];
#pragma unroll
    for (int kc = 0; kc < KC; ++kc)
#pragma unroll
        for (int nt = 0; nt < NTW; ++nt) {
            int nn = n0 + nt * 8 + g;
            int p0 = kc * 8 + i4;
            int p1 = kc * 8 + 4 + i4;
            bh0c[kc][nt] = (p0 < KPH) ? Whi[p0 * NGL + nn] : 0u;
            bh1c[kc][nt] = (p1 < KPH) ? Whi[p1 * NGL + nn] : 0u;
            bl0c[kc][nt] = (p0 < KPH) ? Wlo[p0 * NGL + nn] : 0u;
            bl1c[kc][nt] = (p1 < KPH) ? Wlo[p1 * NGL + nn] : 0u;
        }

#pragma unroll
    for (int mt = 0; mt < 8; ++mt) {
        const int mrow = mt * 16;
        float acc[NTW][4];
#pragma unroll
        for (int nt = 0; nt < NTW; ++nt)
#pragma unroll
            for (int q = 0; q < 4; ++q) acc[nt][q] = 0.0f;

#pragma unroll
        for (int kc = 0; kc < KC; ++kc) {
            const uint4 ah4 = *(const uint4*)&AhiF[((mt * KC + kc) * 32 + lane) * 4];
            const uint4 al4 = *(const uint4*)&AloF[((mt * KC + kc) * 32 + lane) * 4];
            uint32_t ahi[4] = {ah4.x, ah4.y, ah4.z, ah4.w};
            uint32_t alo[4] = {al4.x, al4.y, al4.z, al4.w};
#pragma unroll
            for (int nt = 0; nt < NTW; ++nt) {
                mma_bf16(acc[nt], ahi, bh0c[kc][nt], bh1c[kc][nt]);
                mma_bf16(acc[nt], ahi, bl0c[kc][nt], bl1c[kc][nt]);
                mma_bf16(acc[nt], alo, bh0c[kc][nt], bh1c[kc][nt]);
            }
        }

#pragma unroll
        for (int nt = 0; nt < NTW; ++nt) {
            int n = n0 + nt * 8 + 2 * i4;
            float bx = bias[n], by = bias[n + 1];
            size_t r = (size_t)(m0 + mrow + g);
            *(float2*)&out[r * NGL + n]       = make_float2(acc[nt][0] + bx, acc[nt][1] + by);
            *(float2*)&out[(r + 8) * NGL + n] = make_float2(acc[nt][2] + bx, acc[nt][3] + by);
        }
    }
}

// ---------------------------------------------------------------------------
// L1 recurrence v4 (R14/R10-exact measured-best): (kh:2)x(rg:2)x(u:64), 8 rows,
// scalar FFMA, 2 barriers/step, grid (B/8, 2).
// ---------------------------------------------------------------------------
__global__ void __launch_bounds__(256) lstm_rec_l1(
    const float* __restrict__ xzf, const float* __restrict__ xzb,
    const float* __restrict__ Wrf, const float* __restrict__ Wrb,
    float* __restrict__ out)
{
    constexpr int UP = 68;
    extern __shared__ float sm[];
    float* Wr_s = sm;
    float* hs0  = Wr_s + 64 * 256;
    float* hs1  = hs0 + 8 * UP;
    float4* ps  = (float4*)(hs1 + 8 * UP);

    const int dir = blockIdx.y;
    const float* Wr = dir ? Wrb : Wrf;
    const float* xz = dir ? xzb : xzf;

    const int tid = threadIdx.x;
    const int u   = tid & 63;
    const int r0  = ((tid >> 6) & 1) * 4;
    const int kh  = tid >> 7;
    const int b0  = blockIdx.x * 8;

    for (int i = tid; i < 64 * 256; i += 256) {
        int u2 = i >> 8, c = i & 255, uu = c >> 2, gg = c & 3;
        Wr_s[i] = Wr[u2 * 256 + gg * 64 + uu];
    }
    for (int i = tid; i < 2 * 8 * UP; i += 256) hs0[i] = 0.0f;

    float cst[4], cx[4][4];
#pragma unroll
    for (int j = 0; j < 4; ++j) cst[j] = 0.0f;
    if (kh == 0) {
        const int t0 = dir ? (T_ - 1) : 0;
#pragma unroll
        for (int j = 0; j < 4; ++j) {
            const float* p = xz + ((size_t)(b0 + r0 + j) * T_ + t0) * 256;
#pragma unroll
            for (int gg = 0; gg < 4; ++gg) cx[j][gg] = p[gg * 64 + u];
        }
    }
    __syncthreads();

    const float4* __restrict__ wr4 = (const float4*)Wr_s;
    float* hs_c = hs0; float* hs_n = hs1;

    for (int s = 0; s < T_; ++s) {
        const int t  = dir ? (T_ - 1 - s) : s;
        const int sn = (s + 1 < T_) ? (s + 1) : s;
        const int tn = dir ? (T_ - 1 - sn) : sn;

        float pre[4][4];
        if (kh == 0) {
#pragma unroll
            for (int j = 0; j < 4; ++j) {
                const float* p = xz + ((size_t)(b0 + r0 + j) * T_ + tn) * 256;
#pragma unroll
                for (int gg = 0; gg < 4; ++gg) pre[j][gg] = p[gg * 64 + u];
            }
        }

        float4 a[4];
#pragma unroll
        for (int j = 0; j < 4; ++j) a[j] = make_float4(0, 0, 0, 0);

#pragma unroll
        for (int jj = 0; jj < 8; ++jj) {
            float4 h4[4];
#pragma unroll
            for (int j = 0; j < 4; ++j)
                h4[j] = *(const float4*)&hs_c[(r0 + j) * UP + kh * 32 + jj * 4];
#pragma unroll
            for (int q = 0; q < 4; ++q) {
                float4 wv = wr4[(kh * 32 + jj * 4 + q) * 64 + u];
#pragma unroll
                for (int j = 0; j < 4; ++j) {
                    float hv = (&h4[j].x)[q];
                    a[j].x += hv * wv.x; a[j].y += hv * wv.y;
                    a[j].z += hv * wv.z; a[j].w += hv * wv.w;
                }
            }
        }

        if (kh == 1) {
#pragma unroll
            for (int j = 0; j < 4; ++j) ps[(r0 + j) * 64 + u] = a[j];
        }
        __syncthreads();

        if (kh == 0) {
#pragma unroll
            for (int j = 0; j < 4; ++j) {
                float4 q4 = ps[(r0 + j) * 64 + u];
                float ig = sigf(a[j].x + q4.x + cx[j][0]);
                float fg = sigf(a[j].y + q4.y + cx[j][1]);
                float gg = tanhf_fast(a[j].z + q4.z + cx[j][2]);
                float og = sigf(a[j].w + q4.w + cx[j][3]);
                cst[j] = fg * cst[j] + ig * gg;
                float hn = og * tanhf_fast(cst[j]);
                hs_n[(r0 + j) * UP + u] = hn;
                out[((size_t)(b0 + r0 + j) * T_ + t) * 128 + dir * 64 + u] = hn;
#pragma unroll
                for (int gg2 = 0; gg2 < 4; ++gg2) cx[j][gg2] = pre[j][gg2];
            }
        }
        __syncthreads();
        float* tmp = hs_c; hs_c = hs_n; hs_n = tmp;
    }
}

__global__ void __launch_bounds__(128) lstm_rec_l2(
    const float* __restrict__ xzf, const float* __restrict__ xzb,
    const float* __restrict__ Wrf, const float* __restrict__ Wrb,
    float* __restrict__ out)
{
    __shared__ float hsm[4][2][2][32];

    const int dir = blockIdx.y;
    const float* Wr = dir ? Wrb : Wrf;
    const float* xz = dir ? xzb : xzf;

    const int tid = threadIdx.x, wid = tid >> 5, lane = tid & 31;
    const size_t rb0 = (size_t)(blockIdx.x * 8 + wid * 2) * T_;
    const size_t rb1 = rb0 + T_;

    float4 wq[32];
#pragma unroll
    for (int u2 = 0; u2 < 32; ++u2) {
        const float* wrow = Wr + u2 * 128;
        wq[u2] = make_float4(wrow[lane], wrow[32 + lane], wrow[64 + lane], wrow[96 + lane]);
    }

    float c0 = 0.0f, c1 = 0.0f;
    float4 cx0, cx1;
    {
        const int t0 = dir ? (T_ - 1) : 0;
        const float* p0 = xz + (rb0 + t0) * 128;
        const float* p1 = xz + (rb1 + t0) * 128;
        cx0 = make_float4(p0[lane], p0[32 + lane], p0[64 + lane], p0[96 + lane]);
        cx1 = make_float4(p1[lane], p1[32 + lane], p1[64 + lane], p1[96 + lane]);
    }
    hsm[wid][0][0][lane] = 0.0f;
    hsm[wid][0][1][lane] = 0.0f;
    __syncwarp();

    int p = 0;
    for (int s = 0; s < T_; ++s) {
        const int t  = dir ? (T_ - 1 - s) : s;
        const int sn = (s + 1 < T_) ? (s + 1) : s;
        const int tn = dir ? (T_ - 1 - sn) : sn;

        const float* q0 = xz + (rb0 + tn) * 128;
        const float* q1 = xz + (rb1 + tn) * 128;
        float4 pre0 = make_float4(q0[lane], q0[32 + lane], q0[64 + lane], q0[96 + lane]);
        float4 pre1 = make_float4(q1[lane], q1[32 + lane], q1[64 + lane], q1[96 + lane]);

        float4 a0 = cx0, a1 = cx1;
#pragma unroll
        for (int jj = 0; jj < 8; ++jj) {
            float4 h40 = *(const float4*)&hsm[wid][p][0][jj * 4];
            float4 h41 = *(const float4*)&hsm[wid][p][1][jj * 4];
#pragma unroll
            for (int q = 0; q < 4; ++q) {
                float hv0 = (&h40.x)[q], hv1 = (&h41.x)[q];
                float4 w = wq[jj * 4 + q];
                a0.x += hv0 * w.x; a0.y += hv0 * w.y; a0.z += hv0 * w.z; a0.w += hv0 * w.w;
                a1.x += hv1 * w.x; a1.y += hv1 * w.y; a1.z += hv1 * w.z; a1.w += hv1 * w.w;
            }
        }

        float i0 = sigf(a0.x), f0 = sigf(a0.y), g0 = tanhf_fast(a0.z), o0 = sigf(a0.w);
        c0 = f0 * c0 + i0 * g0;
        float h0 = o0 * tanhf_fast(c0);
        float i1 = sigf(a1.x), f1 = sigf(a1.y), g1 = tanhf_fast(a1.z), o1 = sigf(a1.w);
        c1 = f1 * c1 + i1 * g1;
        float h1 = o1 * tanhf_fast(c1);

        hsm[wid][p ^ 1][0][lane] = h0;
        hsm[wid][p ^ 1][1][lane] = h1;
        out[(rb0 + t) * 64 + dir * 32 + lane] = h0;
        out[(rb1 + t) * 64 + dir * 32 + lane] = h1;
        cx0 = pre0; cx1 = pre1;
        __syncwarp();
        p ^= 1;
    }
}

__global__ void __launch_bounds__(128) lstm_rec_l3(
    const float* __restrict__ xzf, const float* __restrict__ xzb,
    const float* __restrict__ Wrf, const float* __restrict__ Wrb,
    float* __restrict__ out)
{
    __shared__ float hsm[4][2][2][16];

    const int dir = blockIdx.y;
    const float* Wr = dir ? Wrb : Wrf;
    const float* xz = dir ? xzb : xzf;

    const int tid = threadIdx.x, wid = tid >> 5, lane = tid & 31;
    const int r2 = lane >> 4, u = lane & 15;
    const int row = blockIdx.x * 8 + wid * 2 + r2;
    const size_t rb = (size_t)row * T_;

    float4 wq[16];
#pragma unroll
    for (int u2 = 0; u2 < 16; ++u2) {
        const float* wrow = Wr + u2 * 64;
        wq[u2] = make_float4(wrow[u], wrow[16 + u], wrow[32 + u], wrow[48 + u]);
    }

    float cst = 0.0f, h = 0.0f;
    float4 cx;
    {
        const int t0 = dir ? (T_ - 1) : 0;
        const float* p = xz + (rb + t0) * 64;
        cx = make_float4(p[u], p[16 + u], p[32 + u], p[48 + u]);
    }
    hsm[wid][0][r2][u] = 0.0f;
    __syncwarp();

    int p = 0;
    for (int s = 0; s < T_; ++s) {
        const int sn = (s + 1 < T_) ? (s + 1) : s;
        const int tn = dir ? (T_ - 1 - sn) : sn;

        const float* q = xz + (rb + tn) * 64;
        float4 pre = make_float4(q[u], q[16 + u], q[32 + u], q[48 + u]);

        float4 a = cx;
#pragma unroll
        for (int jj = 0; jj < 4; ++jj) {
            float4 h4 = *(const float4*)&hsm[wid][p][r2][jj * 4];
#pragma unroll
            for (int qq = 0; qq < 4; ++qq) {
                float hv = (&h4.x)[qq];
                float4 wv = wq[jj * 4 + qq];
                a.x += hv * wv.x; a.y += hv * wv.y; a.z += hv * wv.z; a.w += hv * wv.w;
            }
        }

        float ig = sigf(a.x), fg = sigf(a.y), gg = tanhf_fast(a.z), og = sigf(a.w);
        cst = fg * cst + ig * gg;
        h = og * tanhf_fast(cst);

        hsm[wid][p ^ 1][r2][u] = h;
        cx = pre;
        __syncwarp();
        p ^= 1;
    }

    out[row * 32 + dir * 16 + u] = h;
}

__global__ void head_kernel(const float* __restrict__ h3,
                            const float* __restrict__ d3w, const float* __restrict__ d3b,
                            const float* __restrict__ cw,  const float* __restrict__ cb,
                            float* __restrict__ out)
{
    int b = blockIdx.x * blockDim.x + threadIdx.x;
    if (b >= B_) return;

    float hv[32];
#pragma unroll
    for (int i = 0; i < 32; ++i) hv[i] = h3[b * 32 + i];

    float d[8];
#pragma unroll
    for (int j = 0; j < 8; ++j) {
        float a = d3b[j];
#pragma unroll
        for (int i = 0; i < 32; ++i) a += hv[i] * d3w[i * 8 + j];
        d[j] = a > 0.0f ? a : 0.0f;
    }
#pragma unroll
    for (int k = 0; k < 3; ++k) {
        float a = cb[k];
#pragma unroll
        for (int j = 0; j < 8; ++j) a += d[j] * cw[j * 3 + k];
        out[b * 3 + k] = 1.0f / (1.0f + expf(-a));
    }
}

extern "C" void kernel_launch(void* const* d_in, const int* in_sizes, int n_in,
                              void* d_out, int out_size)
{
    const float* x     = (const float*)d_in[0];
    const float* w1f_k = (const float*)d_in[1];
    const float* w1f_r = (const float*)d_in[2];
    const float* w1f_b = (const float*)d_in[3];
    const float* w1b_k = (const float*)d_in[4];
    const float* w1b_r = (const float*)d_in[5];
    const float* w1b_b = (const float*)d_in[6];
    const float* w2f_k = (const float*)d_in[7];
    const float* w2f_r = (const float*)d_in[8];
    const float* w2f_b = (const float*)d_in[9];
    const float* w2b_k = (const float*)d_in[10];
    const float* w2b_r = (const float*)d_in[11];
    const float* w2b_b = (const float*)d_in[12];
    const float* w3f_k = (const float*)d_in[13];
    const float* w3f_r = (const float*)d_in[14];
    const float* w3f_b = (const float*)d_in[15];
    const float* w3b_k = (const float*)d_in[16];
    const float* w3b_r = (const float*)d_in[17];
    const float* w3b_b = (const float*)d_in[18];
    const float* d3_w  = (const float*)d_in[19];
    const float* d3_b  = (const float*)d_in[20];
    const float* cls_w = (const float*)d_in[21];
    const float* cls_b = (const float*)d_in[22];

    float *b1, *b2, *b3, *xzf, *xzb;
    uint32_t *p1h, *p1l, *p2h, *p2l, *p3h, *p3l;
    cudaGetSymbolAddress((void**)&b1, g_buf1);
    cudaGetSymbolAddress((void**)&b2, g_buf2);
    cudaGetSymbolAddress((void**)&b3, g_buf3);
    cudaGetSymbolAddress((void**)&xzf, g_xzf);
    cudaGetSymbolAddress((void**)&xzb, g_xzb);
    cudaGetSymbolAddress((void**)&p1h, g_w1h);
    cudaGetSymbolAddress((void**)&p1l, g_w1l);
    cudaGetSymbolAddress((void**)&p2h, g_w2h);
    cudaGetSymbolAddress((void**)&p2l, g_w2l);
    cudaGetSymbolAddress((void**)&p3h, g_w3h);
    cudaGetSymbolAddress((void**)&p3l, g_w3l);

    const size_t gs1 = (size_t)2 * 8 * 5 * 128 * 4;   // 40 KB
    const size_t gs2 = (size_t)2 * 8 * 8 * 128 * 4;   // 64 KB
    const size_t gs3 = (size_t)2 * 8 * 4 * 128 * 4;   // 32 KB
    const size_t rs1 = (size_t)(64 * 256 + 2 * 8 * 68) * 4 + 8 * 64 * 16;

    cudaFuncSetAttribute((const void*)inproj_gemm<78, 80, 256, 16>,
                         cudaFuncAttributeMaxDynamicSharedMemorySize, (int)gs1);
    cudaFuncSetAttribute((const void*)inproj_gemm<128, 128, 128, 16>,
                         cudaFuncAttributeMaxDynamicSharedMemorySize, (int)gs2);
    cudaFuncSetAttribute((const void*)inproj_gemm<64, 64, 64, 8>,
                         cudaFuncAttributeMaxDynamicSharedMemorySize, (int)gs3);
    cudaFuncSetAttribute((const void*)lstm_rec_l1,
                         cudaFuncAttributeMaxDynamicSharedMemorySize, (int)rs1);

    // ---- Pre-pack all weights ----
    pack_w<78, 40, 256><<<dim3((40 * 256 + 255) / 256, 2), 256>>>(w1f_k, w1b_k, p1h, p1l);
    pack_w<128, 64, 128><<<dim3((64 * 128 + 255) / 256, 2), 256>>>(w2f_k, w2b_k, p2h, p2l);
    pack_w<64, 32, 64><<<dim3((32 * 64 + 255) / 256, 2), 256>>>(w3f_k, w3b_k, p3h, p3l);

    // ---- Layer 1 ----
    inproj_gemm<78, 80, 256, 16><<<dim3(MX_ / 128, 2), 512, gs1>>>(
        x, p1h, p1l, w1f_b, w1b_b, xzf, xzb);
    lstm_rec_l1<<<dim3(B_ / 8, 2), 256, rs1>>>(xzf, xzb, w1f_r, w1b_r, b1);

    // ---- Layer 2 ----
    inproj_gemm<128, 128, 128, 16><<<dim3(MX_ / 128, 2), 512, gs2>>>(
        b1, p2h, p2l, w2f_b, w2b_b, xzf, xzb);
    lstm_rec_l2<<<dim3(B_ / 8, 2), 128>>>(xzf, xzb, w2f_r, w2b_r, b2);

    // ---- Layer 3 ----
    inproj_gemm<64, 64, 64, 8><<<dim3(MX_ / 128, 2), 256, gs3>>>(
        b2, p3h, p3l, w3f_b, w3b_b, xzf, xzb);
    lstm_rec_l3<<<dim3(B_ / 8, 2), 128>>>(xzf, xzb, w3f_r, w3b_r, b3);

    // ---- Head ----
    head_kernel<<<(B_ + 255) / 256, 256>>>(b3, d3_w, d3_b, cls_w, cls_b, (float*)d_out);
}